// round 8
// baseline (speedup 1.0000x reference)
#include <cuda_runtime.h>

// ---------------------------------------------------------------------------
// BatchTopK: out = scatter(top_{k*rows}(relu(x))) over the FLATTENED array.
// R7: 4-launch pipeline.
//   K1 sample (+choose in last block)  - pick lower-bound bin L (3x margin)
//   K2 main   (read x once, zero out, stage cands>=L, hist at flush;
//              last block: select 13-bit bucket)
//   K3 scatter(emit >bucket, stage ==bucket + global 8192-bin refine hist;
//              last block: scan + single list pass + exact T + ties)
//   K4 fallback (single block exact path, flag-gated; cleanup)
// All state self-restoring per replay.
// ---------------------------------------------------------------------------

#define HIST_BINS 4096
#define RBINS     8192
#define CAP1      (1u << 21)   // candidate list: 2M * 8B = 16MB
#define CAP2      (1u << 20)   // in-bucket list: 1M * 8B = 8MB
#define EQ_CAP    2048
#define EQF_CAP   1024
#define SSTR4     256          // sample every 256th float4

#define SAMPLE_BLOCKS 128
#define SC_BLOCKS     296
#define SC_BUF        2048

__device__ unsigned int       g_shist[HIST_BINS];
__device__ unsigned int       g_hist[HIST_BINS];
__device__ unsigned int       g_rhist[RBINS];
__device__ unsigned int       g_lbin;
__device__ int                g_bucket;     // -1 keep all positives; HIST_BINS keep none
__device__ unsigned int       g_rem;
__device__ int                g_need_full;
__device__ unsigned int       g_cand_count;
__device__ unsigned int       g_c2_count;
__device__ unsigned int       g_done1, g_done2, g_done3;
__device__ unsigned long long g_cand[CAP1]; // (bits<<32) | flat_index
__device__ unsigned long long g_cand2[CAP2];

// ---------------------------------------------------------------------------
// K1: sampled histogram; last block picks g_lbin, zeroes g_shist.
__global__ void sample_kernel(const float4* __restrict__ x4, int n4, int n,
                              const int* __restrict__ kptr, long long num_samples) {
    __shared__ unsigned int sh[HIST_BINS];
    __shared__ unsigned int ssum[256];
    __shared__ unsigned int s_lbin;
    __shared__ int s_last;
    int t = threadIdx.x;
    for (int i = t; i < HIST_BINS; i += blockDim.x) sh[i] = 0;
    __syncthreads();
    int ns = n4 / SSTR4;
    int stride = gridDim.x * blockDim.x;
    for (int j = blockIdx.x * blockDim.x + t; j < ns; j += stride) {
        float4 v = x4[(size_t)j * SSTR4];
        if (v.x > 0.f) atomicAdd(&sh[__float_as_uint(v.x) >> 19], 1u);
        if (v.y > 0.f) atomicAdd(&sh[__float_as_uint(v.y) >> 19], 1u);
        if (v.z > 0.f) atomicAdd(&sh[__float_as_uint(v.z) >> 19], 1u);
        if (v.w > 0.f) atomicAdd(&sh[__float_as_uint(v.w) >> 19], 1u);
    }
    __syncthreads();
    for (int i = t; i < HIST_BINS; i += blockDim.x) {
        unsigned c = sh[i];
        if (c) atomicAdd(&g_shist[i], c);
    }
    __threadfence();
    if (t == 0) {
        unsigned d = atomicAdd(&g_done1, 1u);
        s_last = (d == gridDim.x - 1u);
    }
    __syncthreads();
    if (!s_last) return;

    // ---- choose (256 threads, 16 bins each) ----
    if (t == 0) s_lbin = 0u;
    unsigned c16[16];
#pragma unroll
    for (int q = 0; q < 16; q++) c16[q] = __ldcg(&g_shist[16 * t + q]);
    unsigned my = 0;
#pragma unroll
    for (int q = 0; q < 16; q++) my += c16[q];
    ssum[t] = my;
    __syncthreads();
    for (int d = 1; d < 256; d <<= 1) {
        unsigned v = ssum[t] + ((t + d < 256) ? ssum[t + d] : 0u);
        __syncthreads();
        ssum[t] = v;
        __syncthreads();
    }
    long long n_keep = (long long)kptr[0] * num_samples;
    long long sampled = (long long)ns * 4;
    if (sampled < 1) sampled = 1;
    long long scale = ((long long)n + sampled - 1) / sampled;
    if (scale < 1) scale = 1;
    long long want = 3 * n_keep;
    long long maxw = (long long)(CAP1 / 2);
    if (want > maxw) want = maxw;
    if (want < 2 * n_keep) want = 2 * n_keep;
    long long tgt = want / scale;
    if (tgt < 512) tgt = 512;
    unsigned target = (tgt > 0x7FFFFFFFLL) ? 0x7FFFFFFFu : (unsigned)tgt;

    unsigned S_after = ssum[t] - my;
    if (S_after < target && S_after + my >= target) {
        unsigned cum = S_after;
        for (int b = 16 * t + 15; b >= 16 * t; --b) {
            unsigned cc = c16[b - 16 * t];
            if (cum + cc >= target) { s_lbin = (unsigned)b; break; }
            cum += cc;
        }
    }
    __syncthreads();
    if (t == 0) { g_lbin = s_lbin; g_done1 = 0u; }
    for (int i = t; i < HIST_BINS; i += blockDim.x) g_shist[i] = 0u;
}

// ---------------------------------------------------------------------------
// K2: fused full pass + hist at flush; last block: select, zero g_hist.
__global__ void main_kernel(const float4* __restrict__ x4, float4* __restrict__ o4,
                            int n4, const float* __restrict__ x, float* __restrict__ o,
                            int n, int total_threads,
                            const int* __restrict__ kptr, long long num_samples) {
    __shared__ unsigned long long sbuf[2176];
    __shared__ unsigned int ssum[256];
    __shared__ unsigned int s_cnt, s_base;
    __shared__ int s_last;
    int t = threadIdx.x;
    if (t == 0) s_cnt = 0;
    __syncthreads();

    unsigned lbits = g_lbin << 19;
    int gtid = blockIdx.x * blockDim.x + t;
    int i1 = gtid, i2 = gtid + total_threads;
    bool b1 = i1 < n4, b2 = i2 < n4;
    float4 v1 = make_float4(0.f,0.f,0.f,0.f), v2 = v1;
    if (b1) v1 = __ldcs(&x4[i1]);
    if (b2) v2 = __ldcs(&x4[i2]);
    float4 z = make_float4(0.f, 0.f, 0.f, 0.f);
    if (b1) __stcs(&o4[i1], z);
    if (b2) __stcs(&o4[i2], z);

#define PUSH(val, gi)                                                     \
    { unsigned _u = __float_as_uint(val);                                 \
      if ((val) > 0.f && _u >= lbits) {                                   \
          unsigned _p = atomicAdd(&s_cnt, 1u);                            \
          sbuf[_p] = ((unsigned long long)_u << 32) |                     \
                     (unsigned long long)(gi); } }
    if (b1) {
        unsigned base = (unsigned)i1 * 4u;
        PUSH(v1.x, base + 0u); PUSH(v1.y, base + 1u);
        PUSH(v1.z, base + 2u); PUSH(v1.w, base + 3u);
    }
    if (b2) {
        unsigned base = (unsigned)i2 * 4u;
        PUSH(v2.x, base + 0u); PUSH(v2.y, base + 1u);
        PUSH(v2.z, base + 2u); PUSH(v2.w, base + 3u);
    }
    int t0 = n4 * 4 + gtid;
    if (t0 < n) {
        float s = x[t0];
        o[t0] = 0.f;
        PUSH(s, (unsigned)t0);
    }
#undef PUSH
    __syncthreads();

    unsigned cnt = s_cnt;
    if (cnt) {
        if (t == 0) {
            s_base = atomicAdd(&g_cand_count, cnt);
            if (s_base + cnt > CAP1) g_need_full = 1;
        }
        __syncthreads();
        unsigned gb = s_base;
        for (unsigned j = t; j < cnt; j += blockDim.x) {
            unsigned p = gb + j;
            unsigned long long cv = sbuf[j];
            if (p < CAP1) {
                g_cand[p] = cv;
                atomicAdd(&g_hist[(unsigned)(cv >> 51)], 1u);
            }
        }
    }
    __threadfence();
    if (t == 0) {
        unsigned d = atomicAdd(&g_done2, 1u);
        s_last = (d == gridDim.x - 1u);
    }
    __syncthreads();
    if (!s_last) return;

    // ---- select (256 threads, 16 bins each) ----
    int nf = __ldcg(&g_need_full);
    long long n_keep = (long long)kptr[0] * num_samples;
    if (!nf) {
        if (n_keep <= 0) {
            if (t == 0) { g_bucket = HIST_BINS; g_rem = 0; }
        } else {
            unsigned c16[16];
#pragma unroll
            for (int q = 0; q < 16; q++) c16[q] = __ldcg(&g_hist[16 * t + q]);
            unsigned my = 0;
#pragma unroll
            for (int q = 0; q < 16; q++) my += c16[q];
            ssum[t] = my;
            __syncthreads();
            for (int d = 1; d < 256; d <<= 1) {
                unsigned v = ssum[t] + ((t + d < 256) ? ssum[t + d] : 0u);
                __syncthreads();
                ssum[t] = v;
                __syncthreads();
            }
            unsigned total = ssum[0];
            unsigned S_after = ssum[t] - my;
            if ((long long)total < n_keep) {
                if (t == 0) {
                    if (g_lbin == 0u) { g_bucket = -1; g_rem = 0; }
                    else              { g_need_full = 1; }
                }
            } else if ((long long)S_after < n_keep &&
                       (long long)S_after + (long long)my >= n_keep) {
                unsigned cum = S_after;
                for (int b = 16 * t + 15; b >= 16 * t; --b) {
                    unsigned cc = c16[b - 16 * t];
                    if ((long long)cum + (long long)cc >= n_keep) {
                        g_bucket = b;
                        g_rem = (unsigned)(n_keep - (long long)cum);
                        break;
                    }
                    cum += cc;
                }
            }
            __syncthreads();
        }
    }
    for (int i = t; i < HIST_BINS; i += blockDim.x) g_hist[i] = 0u;
    if (t == 0) g_done2 = 0u;
}

// ---------------------------------------------------------------------------
// K3: grid-wide scatter + in-bucket staging + global refine hist;
//     last block: scan + single list pass + exact threshold + ties.
__global__ void scatter_kernel(float* __restrict__ out) {
    __shared__ unsigned long long sbuf2[SC_BUF];
    __shared__ unsigned long long eq[EQ_CAP];
    __shared__ unsigned int ssum[1024];
    __shared__ unsigned int bin64[64];
    __shared__ unsigned int misc[8];
    __shared__ unsigned int s_cnt, s_base;
    __shared__ int s_last, s_over;
    int t = threadIdx.x;
    if (t == 0) { s_cnt = 0; s_over = 0; }
    __syncthreads();

    int nf = __ldcg(&g_need_full);
    int bucket = g_bucket;
    bool work = (!nf) && bucket != HIST_BINS;
    if (work) {
        unsigned m = min(g_cand_count, CAP1);
        unsigned stride = gridDim.x * blockDim.x;
        for (unsigned j = blockIdx.x * blockDim.x + t; j < m; j += stride) {
            unsigned long long cv = g_cand[j];
            unsigned u   = (unsigned)(cv >> 32);
            unsigned idx = (unsigned)cv;
            int bin = (int)(u >> 19);
            if (bucket == -1 || bin > bucket) {
                out[idx] = __uint_as_float(u);
            } else if (bin == bucket) {
                unsigned p = atomicAdd(&s_cnt, 1u);
                if (p < SC_BUF) {
                    sbuf2[p] = cv;
                    atomicAdd(&g_rhist[(u >> 6) & 0x1FFFu], 1u);
                } else {
                    s_over = 1;
                }
            }
        }
        __syncthreads();
        unsigned cnt = min(s_cnt, (unsigned)SC_BUF);
        if (s_over && t == 0) g_need_full = 1;
        if (cnt) {
            if (t == 0) s_base = atomicAdd(&g_c2_count, cnt);
            __syncthreads();
            unsigned gb = s_base;
            for (unsigned j = t; j < cnt; j += blockDim.x) {
                unsigned p = gb + j;
                if (p < CAP2) g_cand2[p] = sbuf2[j];
            }
        }
    }
    __threadfence();
    if (t == 0) {
        unsigned d = atomicAdd(&g_done3, 1u);
        s_last = (d == gridDim.x - 1u);
    }
    __syncthreads();
    if (!s_last) return;
    if (t == 0) g_done3 = 0u;

    int nf2 = __ldcg(&g_need_full);
    if (!nf2 && work && bucket >= 0) {
        unsigned r = g_rem;
        // ---- suffix scan of g_rhist (1024 threads, 8 bins each) ----
        unsigned c8[8];
#pragma unroll
        for (int q = 0; q < 8; q++) c8[q] = __ldcg(&g_rhist[8 * t + q]);
        unsigned my = 0;
#pragma unroll
        for (int q = 0; q < 8; q++) my += c8[q];
        ssum[t] = my;
        __syncthreads();
        for (int d = 1; d < 1024; d <<= 1) {
            unsigned v = ssum[t] + ((t + d < 1024) ? ssum[t + d] : 0u);
            __syncthreads();
            ssum[t] = v;
            __syncthreads();
        }
        unsigned S_after = ssum[t] - my;
        if (S_after < r && S_after + my >= r) {
            unsigned cum = S_after;
            for (int b = 8 * t + 7; b >= 8 * t; --b) {
                unsigned cc = c8[b - 8 * t];
                if (cum + cc >= r) {
                    misc[0] = (unsigned)b; misc[1] = r - cum;
                    misc[2] = cc;          // count at b1
                    break;
                }
                cum += cc;
            }
        }
        __syncthreads();
        unsigned b1 = misc[0], r1 = misc[1], cnt_b1 = misc[2];
        if (cnt_b1 > EQ_CAP) {
            if (t == 0) g_need_full = 1;
        } else {
            if (t == 0) misc[3] = 0;
            if (t < 64) bin64[t] = 0;
            __syncthreads();
            // ---- ONE pass over in-bucket list ----
            unsigned m2 = min(__ldcg(&g_c2_count), CAP2);
            for (unsigned i = t; i < m2; i += 1024) {
                unsigned long long cv = __ldcg(&g_cand2[i]);
                unsigned u   = (unsigned)(cv >> 32);
                unsigned idx = (unsigned)cv;
                unsigned sub = (u >> 6) & 0x1FFFu;
                if (sub > b1) {
                    out[idx] = __uint_as_float(u);
                } else if (sub == b1) {
                    unsigned p = atomicAdd(&misc[3], 1u);
                    eq[p] = cv;
                    atomicAdd(&bin64[u & 0x3Fu], 1u);
                }
            }
            __syncthreads();
            unsigned ec = misc[3];
            if (t == 0) {
                unsigned cum = 0, rr = r1, b2 = 0;
                for (int i = 63; i >= 0; --i) {
                    unsigned cc = bin64[i];
                    if (cum + cc >= rr) { b2 = (unsigned)i; rr -= cum; break; }
                    cum += cc;
                }
                misc[4] = b2; misc[5] = rr;
            }
            __syncthreads();
            unsigned b2 = misc[4], r2 = misc[5];
            unsigned T = ((unsigned)bucket << 19) | (b1 << 6) | b2;
            for (unsigned i = t; i < ec; i += 1024) {
                unsigned long long cv = eq[i];
                unsigned u   = (unsigned)(cv >> 32);
                unsigned idx = (unsigned)cv;
                if (u > T) {
                    out[idx] = __uint_as_float(u);
                } else if (u == T) {
                    unsigned rank = 0;
                    for (unsigned j = 0; j < ec; ++j) {
                        unsigned long long cj = eq[j];
                        if ((unsigned)(cj >> 32) == T && (unsigned)cj < idx) rank++;
                    }
                    if (rank < r2) out[idx] = __uint_as_float(u);
                }
            }
        }
    }
    __syncthreads();
    for (int i = t; i < RBINS; i += 1024) g_rhist[i] = 0u;
}

// ---------------------------------------------------------------------------
// K4: single-block exact fallback (only if g_need_full) + state cleanup.
__global__ void fallback_kernel(const float4* __restrict__ x4, int n4,
                                const float* __restrict__ x, int n,
                                const int* __restrict__ kptr, long long num_samples,
                                float* __restrict__ out) {
    __shared__ unsigned int sh[RBINS];          // 32KB: 4096-hist then 8192-hist
    __shared__ unsigned long long eqf[EQF_CAP]; // 8KB
    __shared__ unsigned int misc[8];
    int t = threadIdx.x;
    if (g_need_full) {
        // exact 4096-bin histogram of all positives
        for (int i = t; i < HIST_BINS; i += 1024) sh[i] = 0;
        __syncthreads();
        for (int i = t; i < n4; i += 1024) {
            float4 v = x4[i];
            if (v.x > 0.f) atomicAdd(&sh[__float_as_uint(v.x) >> 19], 1u);
            if (v.y > 0.f) atomicAdd(&sh[__float_as_uint(v.y) >> 19], 1u);
            if (v.z > 0.f) atomicAdd(&sh[__float_as_uint(v.z) >> 19], 1u);
            if (v.w > 0.f) atomicAdd(&sh[__float_as_uint(v.w) >> 19], 1u);
        }
        for (int t0 = n4 * 4 + t; t0 < n; t0 += 1024) {
            float v = x[t0];
            if (v > 0.f) atomicAdd(&sh[__float_as_uint(v) >> 19], 1u);
        }
        __syncthreads();
        if (t == 0) {
            long long n_keep = (long long)kptr[0] * num_samples;
            if (n_keep <= 0) { g_bucket = HIST_BINS; g_rem = 0; }
            else {
                long long cum = 0;
                int bkt = -1; unsigned rem = 0;
                for (int i = HIST_BINS - 1; i >= 0; --i) {
                    unsigned c = sh[i];
                    if (cum + (long long)c >= n_keep) {
                        bkt = i; rem = (unsigned)(n_keep - cum); break;
                    }
                    cum += c;
                }
                g_bucket = bkt; g_rem = rem;
            }
            g_c2_count = 0;
        }
        __syncthreads();
        int bucket = g_bucket;
        unsigned r = g_rem;
        if (bucket != HIST_BINS) {
            for (int i = t; i < n; i += 1024) {
                float s = x[i];
                if (s > 0.f) {
                    unsigned u = __float_as_uint(s);
                    int bin = (int)(u >> 19);
                    if (bucket == -1 || bin > bucket) out[i] = s;
                    else if (bin == bucket) {
                        unsigned p = atomicAdd(&g_c2_count, 1u);
                        if (p < CAP2)
                            g_cand2[p] = ((unsigned long long)u << 32) |
                                         (unsigned long long)(unsigned)i;
                    }
                }
            }
            __syncthreads();
            if (bucket >= 0) {
                unsigned m = min(g_c2_count, CAP2);
                // 8192-bin refine of bits [18:6]
                for (int i = t; i < RBINS; i += 1024) sh[i] = 0;
                __syncthreads();
                for (unsigned i = t; i < m; i += 1024) {
                    unsigned u = (unsigned)(g_cand2[i] >> 32);
                    atomicAdd(&sh[(u >> 6) & 0x1FFFu], 1u);
                }
                __syncthreads();
                if (t == 0) {
                    unsigned cum = 0, rr = r, b1 = 0;
                    for (int i = RBINS - 1; i >= 0; --i) {
                        unsigned cc = sh[i];
                        if (cum + cc >= rr) { b1 = (unsigned)i; rr -= cum; break; }
                        cum += cc;
                    }
                    misc[0] = b1; misc[1] = rr; misc[2] = 0;
                }
                __syncthreads();
                unsigned b1 = misc[0], r1 = misc[1];
                if (t < 64) sh[t] = 0;
                __syncthreads();
                for (unsigned i = t; i < m; i += 1024) {
                    unsigned long long cv = g_cand2[i];
                    unsigned u = (unsigned)(cv >> 32);
                    if (((u >> 6) & 0x1FFFu) == b1) {
                        unsigned p = atomicAdd(&misc[2], 1u);
                        if (p < EQF_CAP) eqf[p] = cv;
                        atomicAdd(&sh[u & 0x3Fu], 1u);
                    }
                }
                __syncthreads();
                unsigned ec = min(misc[2], (unsigned)EQF_CAP);
                if (t == 0) {
                    unsigned cum = 0, rr = r1, b2 = 0;
                    for (int i = 63; i >= 0; --i) {
                        unsigned cc = sh[i];
                        if (cum + cc >= rr) { b2 = (unsigned)i; rr -= cum; break; }
                        cum += cc;
                    }
                    misc[3] = b2; misc[4] = rr;
                }
                __syncthreads();
                unsigned b2 = misc[3], r2 = misc[4];
                unsigned T = ((unsigned)bucket << 19) | (b1 << 6) | b2;
                // emit items in b1 sub-bin: > T directly, == T by index rank
                for (unsigned i = t; i < ec; i += 1024) {
                    unsigned long long cv = eqf[i];
                    unsigned u   = (unsigned)(cv >> 32);
                    unsigned idx = (unsigned)cv;
                    if (u > T) out[idx] = __uint_as_float(u);
                    else if (u == T) {
                        unsigned rank = 0;
                        for (unsigned j = 0; j < ec; ++j) {
                            unsigned long long cj = eqf[j];
                            if ((unsigned)(cj >> 32) == T && (unsigned)cj < idx) rank++;
                        }
                        if (rank < r2) out[idx] = __uint_as_float(u);
                    }
                }
                __syncthreads();
                // items in sub-bins > b1 (all > T): emit
                for (unsigned i = t; i < m; i += 1024) {
                    unsigned long long cv = g_cand2[i];
                    unsigned u = (unsigned)(cv >> 32);
                    if (((u >> 6) & 0x1FFFu) > b1)
                        out[(unsigned)cv] = __uint_as_float(u);
                }
            }
        }
    }
    __syncthreads();
    if (t == 0) { g_need_full = 0; g_cand_count = 0; g_c2_count = 0; }
}

// ---------------------------------------------------------------------------
extern "C" void kernel_launch(void* const* d_in, const int* in_sizes, int n_in,
                              void* d_out, int out_size) {
    const float* x  = (const float*)d_in[0];
    const int*   kp = (const int*)d_in[1];
    int n = in_sizes[0];
    long long num_samples = (long long)n / 16384;  // last dim = 16384
    int n4 = n / 4;

    sample_kernel<<<SAMPLE_BLOCKS, 256>>>((const float4*)x, n4, n, kp, num_samples);

    int mb = (n4 + 511) / 512;
    if (mb < 1) mb = 1;
    int total_threads = mb * 256;
    main_kernel<<<mb, 256>>>((const float4*)x, (float4*)d_out, n4,
                             x, (float*)d_out, n, total_threads, kp, num_samples);

    scatter_kernel<<<SC_BLOCKS, 1024>>>((float*)d_out);
    fallback_kernel<<<1, 1024>>>((const float4*)x, n4, x, n, kp, num_samples,
                                 (float*)d_out);
}

// round 9
// speedup vs baseline: 1.6834x; 1.6834x over previous
#include <cuda_runtime.h>

// ---------------------------------------------------------------------------
// BatchTopK: out = scatter(top_{k*rows}(relu(x))) over the FLATTENED array.
// R9: 5-launch pipeline = R6's main/candhist (no skewed global atomics) +
// R8's distributed scatter/refine (no one-block 50us tail).
//   K1 sample (+choose in last block)   - lower-bound bin L, 3x margin
//   K2 main    - read x once, zero out, SMEM-stage cands>=L, plain flush
//   K3 candhist(+select in last block)  - SMEM 4096-bin hist -> bucket
//   K4 scatter - emit >bucket, stage ==bucket, grid-parallel 8192-bin rhist;
//                last block: scan + ONE list pass + exact T + ties
//   K5 fallback (single block exact path, flag-gated; cleanup)
// Lesson (R4, R8): skewed-key global atomics serialize ~0.854cyc/op on one
// L2 address; all histogram merges must go through per-block SMEM.
// ---------------------------------------------------------------------------

#define HIST_BINS 4096
#define RBINS     8192
#define CAP1      (1u << 21)   // candidate list: 2M * 8B = 16MB
#define CAP2      (1u << 20)   // in-bucket list: 1M * 8B = 8MB
#define EQ_CAP    2048
#define EQF_CAP   1024
#define SSTR4     256          // sample every 256th float4

#define SAMPLE_BLOCKS 128
#define CH_BLOCKS     256
#define SC_BLOCKS     296
#define SC_BUF        2048

__device__ unsigned int       g_shist[HIST_BINS];
__device__ unsigned int       g_hist[HIST_BINS];
__device__ unsigned int       g_rhist[RBINS];
__device__ unsigned int       g_lbin;
__device__ int                g_bucket;     // -1 keep all positives; HIST_BINS keep none
__device__ unsigned int       g_rem;
__device__ int                g_need_full;
__device__ unsigned int       g_cand_count;
__device__ unsigned int       g_c2_count;
__device__ unsigned int       g_done1, g_done2, g_done3;
__device__ unsigned long long g_cand[CAP1]; // (bits<<32) | flat_index
__device__ unsigned long long g_cand2[CAP2];

// ---------------------------------------------------------------------------
// K1: sampled histogram; last block picks g_lbin, zeroes g_shist.
__global__ void sample_kernel(const float4* __restrict__ x4, int n4, int n,
                              const int* __restrict__ kptr, long long num_samples) {
    __shared__ unsigned int sh[HIST_BINS];
    __shared__ unsigned int ssum[256];
    __shared__ unsigned int s_lbin;
    __shared__ int s_last;
    int t = threadIdx.x;
    for (int i = t; i < HIST_BINS; i += blockDim.x) sh[i] = 0;
    __syncthreads();
    int ns = n4 / SSTR4;
    int stride = gridDim.x * blockDim.x;
    for (int j = blockIdx.x * blockDim.x + t; j < ns; j += stride) {
        float4 v = x4[(size_t)j * SSTR4];
        if (v.x > 0.f) atomicAdd(&sh[__float_as_uint(v.x) >> 19], 1u);
        if (v.y > 0.f) atomicAdd(&sh[__float_as_uint(v.y) >> 19], 1u);
        if (v.z > 0.f) atomicAdd(&sh[__float_as_uint(v.z) >> 19], 1u);
        if (v.w > 0.f) atomicAdd(&sh[__float_as_uint(v.w) >> 19], 1u);
    }
    __syncthreads();
    for (int i = t; i < HIST_BINS; i += blockDim.x) {
        unsigned c = sh[i];
        if (c) atomicAdd(&g_shist[i], c);
    }
    __threadfence();
    if (t == 0) {
        unsigned d = atomicAdd(&g_done1, 1u);
        s_last = (d == gridDim.x - 1u);
    }
    __syncthreads();
    if (!s_last) return;

    // ---- choose (256 threads, 16 bins each) ----
    if (t == 0) s_lbin = 0u;
    unsigned c16[16];
#pragma unroll
    for (int q = 0; q < 16; q++) c16[q] = __ldcg(&g_shist[16 * t + q]);
    unsigned my = 0;
#pragma unroll
    for (int q = 0; q < 16; q++) my += c16[q];
    ssum[t] = my;
    __syncthreads();
    for (int d = 1; d < 256; d <<= 1) {
        unsigned v = ssum[t] + ((t + d < 256) ? ssum[t + d] : 0u);
        __syncthreads();
        ssum[t] = v;
        __syncthreads();
    }
    long long n_keep = (long long)kptr[0] * num_samples;
    long long sampled = (long long)ns * 4;
    if (sampled < 1) sampled = 1;
    long long scale = ((long long)n + sampled - 1) / sampled;
    if (scale < 1) scale = 1;
    long long want = 3 * n_keep;
    long long maxw = (long long)(CAP1 / 2);
    if (want > maxw) want = maxw;
    if (want < 2 * n_keep) want = 2 * n_keep;
    long long tgt = want / scale;
    if (tgt < 512) tgt = 512;
    unsigned target = (tgt > 0x7FFFFFFFLL) ? 0x7FFFFFFFu : (unsigned)tgt;

    unsigned S_after = ssum[t] - my;
    if (S_after < target && S_after + my >= target) {
        unsigned cum = S_after;
        for (int b = 16 * t + 15; b >= 16 * t; --b) {
            unsigned cc = c16[b - 16 * t];
            if (cum + cc >= target) { s_lbin = (unsigned)b; break; }
            cum += cc;
        }
    }
    __syncthreads();
    if (t == 0) { g_lbin = s_lbin; g_done1 = 0u; }
    for (int i = t; i < HIST_BINS; i += blockDim.x) g_shist[i] = 0u;
}

// ---------------------------------------------------------------------------
// K2: fused full pass, SMEM staging, plain flush. NO global hist, NO done.
__global__ void main_kernel(const float4* __restrict__ x4, float4* __restrict__ o4,
                            int n4, const float* __restrict__ x, float* __restrict__ o,
                            int n, int total_threads) {
    __shared__ unsigned long long sbuf[2176];
    __shared__ unsigned int s_cnt, s_base;
    int t = threadIdx.x;
    if (t == 0) s_cnt = 0;
    __syncthreads();

    unsigned lbits = g_lbin << 19;
    int gtid = blockIdx.x * blockDim.x + t;
    int i1 = gtid, i2 = gtid + total_threads;
    bool b1 = i1 < n4, b2 = i2 < n4;
    float4 v1 = make_float4(0.f,0.f,0.f,0.f), v2 = v1;
    if (b1) v1 = __ldcs(&x4[i1]);
    if (b2) v2 = __ldcs(&x4[i2]);
    float4 z = make_float4(0.f, 0.f, 0.f, 0.f);
    if (b1) __stcs(&o4[i1], z);
    if (b2) __stcs(&o4[i2], z);

#define PUSH(val, gi)                                                     \
    { unsigned _u = __float_as_uint(val);                                 \
      if ((val) > 0.f && _u >= lbits) {                                   \
          unsigned _p = atomicAdd(&s_cnt, 1u);                            \
          sbuf[_p] = ((unsigned long long)_u << 32) |                     \
                     (unsigned long long)(gi); } }
    if (b1) {
        unsigned base = (unsigned)i1 * 4u;
        PUSH(v1.x, base + 0u); PUSH(v1.y, base + 1u);
        PUSH(v1.z, base + 2u); PUSH(v1.w, base + 3u);
    }
    if (b2) {
        unsigned base = (unsigned)i2 * 4u;
        PUSH(v2.x, base + 0u); PUSH(v2.y, base + 1u);
        PUSH(v2.z, base + 2u); PUSH(v2.w, base + 3u);
    }
    int t0 = n4 * 4 + gtid;
    if (t0 < n) {
        float s = x[t0];
        o[t0] = 0.f;
        PUSH(s, (unsigned)t0);
    }
#undef PUSH
    __syncthreads();

    unsigned cnt = s_cnt;
    if (cnt == 0) return;
    if (t == 0) {
        s_base = atomicAdd(&g_cand_count, cnt);
        if (s_base + cnt > CAP1) g_need_full = 1;
    }
    __syncthreads();
    unsigned gb = s_base;
    for (unsigned j = t; j < cnt; j += blockDim.x) {
        unsigned p = gb + j;
        if (p < CAP1) g_cand[p] = sbuf[j];
    }
}

// ---------------------------------------------------------------------------
// K3: SMEM 4096-bin hist over candidates; last block selects bucket, zeroes.
__global__ void candhist_kernel(const int* __restrict__ kptr, long long num_samples) {
    __shared__ unsigned int sh[HIST_BINS];
    __shared__ unsigned int ssum[256];
    __shared__ int s_last;
    int t = threadIdx.x;
    int nf = __ldcg(&g_need_full);
    if (!nf) {
        for (int i = t; i < HIST_BINS; i += blockDim.x) sh[i] = 0;
        __syncthreads();
        unsigned m = min(g_cand_count, CAP1);
        unsigned stride = gridDim.x * blockDim.x;
        for (unsigned j = blockIdx.x * blockDim.x + t; j < m; j += stride) {
            unsigned u = (unsigned)(g_cand[j] >> 32);
            atomicAdd(&sh[u >> 19], 1u);
        }
        __syncthreads();
        for (int i = t; i < HIST_BINS; i += blockDim.x) {
            unsigned c = sh[i];
            if (c) atomicAdd(&g_hist[i], c);
        }
    }
    __threadfence();
    if (t == 0) {
        unsigned d = atomicAdd(&g_done2, 1u);
        s_last = (d == gridDim.x - 1u);
    }
    __syncthreads();
    if (!s_last) return;

    // ---- select (256 threads, 16 bins each) ----
    long long n_keep = (long long)kptr[0] * num_samples;
    if (!nf) {
        if (n_keep <= 0) {
            if (t == 0) { g_bucket = HIST_BINS; g_rem = 0; }
        } else {
            unsigned c16[16];
#pragma unroll
            for (int q = 0; q < 16; q++) c16[q] = __ldcg(&g_hist[16 * t + q]);
            unsigned my = 0;
#pragma unroll
            for (int q = 0; q < 16; q++) my += c16[q];
            ssum[t] = my;
            __syncthreads();
            for (int d = 1; d < 256; d <<= 1) {
                unsigned v = ssum[t] + ((t + d < 256) ? ssum[t + d] : 0u);
                __syncthreads();
                ssum[t] = v;
                __syncthreads();
            }
            unsigned total = ssum[0];
            unsigned S_after = ssum[t] - my;
            if ((long long)total < n_keep) {
                if (t == 0) {
                    if (g_lbin == 0u) { g_bucket = -1; g_rem = 0; }
                    else              { g_need_full = 1; }
                }
            } else if ((long long)S_after < n_keep &&
                       (long long)S_after + (long long)my >= n_keep) {
                unsigned cum = S_after;
                for (int b = 16 * t + 15; b >= 16 * t; --b) {
                    unsigned cc = c16[b - 16 * t];
                    if ((long long)cum + (long long)cc >= n_keep) {
                        g_bucket = b;
                        g_rem = (unsigned)(n_keep - (long long)cum);
                        break;
                    }
                    cum += cc;
                }
            }
            __syncthreads();
        }
    }
    for (int i = t; i < HIST_BINS; i += blockDim.x) g_hist[i] = 0u;
    if (t == 0) g_done2 = 0u;
}

// ---------------------------------------------------------------------------
// K4: grid-wide scatter + in-bucket staging + grid-parallel refine hist;
//     last block: scan + single list pass + exact threshold + ties.
__global__ void scatter_kernel(float* __restrict__ out) {
    __shared__ unsigned long long sbuf2[SC_BUF];
    __shared__ unsigned long long eq[EQ_CAP];
    __shared__ unsigned int ssum[1024];
    __shared__ unsigned int bin64[64];
    __shared__ unsigned int misc[8];
    __shared__ unsigned int s_cnt, s_base;
    __shared__ int s_last, s_over;
    int t = threadIdx.x;
    if (t == 0) { s_cnt = 0; s_over = 0; }
    __syncthreads();

    int nf = __ldcg(&g_need_full);
    int bucket = g_bucket;
    bool work = (!nf) && bucket != HIST_BINS;
    if (work) {
        unsigned m = min(g_cand_count, CAP1);
        unsigned stride = gridDim.x * blockDim.x;
        for (unsigned j = blockIdx.x * blockDim.x + t; j < m; j += stride) {
            unsigned long long cv = g_cand[j];
            unsigned u   = (unsigned)(cv >> 32);
            unsigned idx = (unsigned)cv;
            int bin = (int)(u >> 19);
            if (bucket == -1 || bin > bucket) {
                out[idx] = __uint_as_float(u);
            } else if (bin == bucket) {
                unsigned p = atomicAdd(&s_cnt, 1u);
                if (p < SC_BUF) {
                    sbuf2[p] = cv;
                    atomicAdd(&g_rhist[(u >> 6) & 0x1FFFu], 1u);  // ~uniform keys
                } else {
                    s_over = 1;
                }
            }
        }
        __syncthreads();
        unsigned cnt = min(s_cnt, (unsigned)SC_BUF);
        if (s_over && t == 0) g_need_full = 1;
        if (cnt) {
            if (t == 0) s_base = atomicAdd(&g_c2_count, cnt);
            __syncthreads();
            unsigned gb = s_base;
            for (unsigned j = t; j < cnt; j += blockDim.x) {
                unsigned p = gb + j;
                if (p < CAP2) g_cand2[p] = sbuf2[j];
            }
        }
    }
    __threadfence();
    if (t == 0) {
        unsigned d = atomicAdd(&g_done3, 1u);
        s_last = (d == gridDim.x - 1u);
    }
    __syncthreads();
    if (!s_last) return;
    if (t == 0) g_done3 = 0u;

    int nf2 = __ldcg(&g_need_full);
    if (!nf2 && work && bucket >= 0) {
        unsigned r = g_rem;
        // ---- suffix scan of g_rhist (1024 threads, 8 bins each) ----
        unsigned c8[8];
#pragma unroll
        for (int q = 0; q < 8; q++) c8[q] = __ldcg(&g_rhist[8 * t + q]);
        unsigned my = 0;
#pragma unroll
        for (int q = 0; q < 8; q++) my += c8[q];
        ssum[t] = my;
        __syncthreads();
        for (int d = 1; d < 1024; d <<= 1) {
            unsigned v = ssum[t] + ((t + d < 1024) ? ssum[t + d] : 0u);
            __syncthreads();
            ssum[t] = v;
            __syncthreads();
        }
        unsigned S_after = ssum[t] - my;
        if (S_after < r && S_after + my >= r) {
            unsigned cum = S_after;
            for (int b = 8 * t + 7; b >= 8 * t; --b) {
                unsigned cc = c8[b - 8 * t];
                if (cum + cc >= r) {
                    misc[0] = (unsigned)b; misc[1] = r - cum;
                    misc[2] = cc;          // count at b1
                    break;
                }
                cum += cc;
            }
        }
        __syncthreads();
        unsigned b1 = misc[0], r1 = misc[1], cnt_b1 = misc[2];
        if (cnt_b1 > EQ_CAP) {
            if (t == 0) g_need_full = 1;
        } else {
            if (t == 0) misc[3] = 0;
            if (t < 64) bin64[t] = 0;
            __syncthreads();
            // ---- ONE pass over in-bucket list ----
            unsigned m2 = min(__ldcg(&g_c2_count), CAP2);
            for (unsigned i = t; i < m2; i += 1024) {
                unsigned long long cv = __ldcg(&g_cand2[i]);
                unsigned u   = (unsigned)(cv >> 32);
                unsigned idx = (unsigned)cv;
                unsigned sub = (u >> 6) & 0x1FFFu;
                if (sub > b1) {
                    out[idx] = __uint_as_float(u);
                } else if (sub == b1) {
                    unsigned p = atomicAdd(&misc[3], 1u);
                    eq[p] = cv;
                    atomicAdd(&bin64[u & 0x3Fu], 1u);
                }
            }
            __syncthreads();
            unsigned ec = misc[3];
            if (t == 0) {
                unsigned cum = 0, rr = r1, b2 = 0;
                for (int i = 63; i >= 0; --i) {
                    unsigned cc = bin64[i];
                    if (cum + cc >= rr) { b2 = (unsigned)i; rr -= cum; break; }
                    cum += cc;
                }
                misc[4] = b2; misc[5] = rr;
            }
            __syncthreads();
            unsigned b2 = misc[4], r2 = misc[5];
            unsigned T = ((unsigned)bucket << 19) | (b1 << 6) | b2;
            for (unsigned i = t; i < ec; i += 1024) {
                unsigned long long cv = eq[i];
                unsigned u   = (unsigned)(cv >> 32);
                unsigned idx = (unsigned)cv;
                if (u > T) {
                    out[idx] = __uint_as_float(u);
                } else if (u == T) {
                    unsigned rank = 0;
                    for (unsigned j = 0; j < ec; ++j) {
                        unsigned long long cj = eq[j];
                        if ((unsigned)(cj >> 32) == T && (unsigned)cj < idx) rank++;
                    }
                    if (rank < r2) out[idx] = __uint_as_float(u);
                }
            }
        }
    }
    __syncthreads();
    for (int i = t; i < RBINS; i += 1024) g_rhist[i] = 0u;
}

// ---------------------------------------------------------------------------
// K5: single-block exact fallback (only if g_need_full) + state cleanup.
__global__ void fallback_kernel(const float4* __restrict__ x4, int n4,
                                const float* __restrict__ x, int n,
                                const int* __restrict__ kptr, long long num_samples,
                                float* __restrict__ out) {
    __shared__ unsigned int sh[RBINS];          // 32KB: 4096-hist then 8192-hist
    __shared__ unsigned long long eqf[EQF_CAP]; // 8KB
    __shared__ unsigned int misc[8];
    int t = threadIdx.x;
    if (g_need_full) {
        for (int i = t; i < HIST_BINS; i += 1024) sh[i] = 0;
        __syncthreads();
        for (int i = t; i < n4; i += 1024) {
            float4 v = x4[i];
            if (v.x > 0.f) atomicAdd(&sh[__float_as_uint(v.x) >> 19], 1u);
            if (v.y > 0.f) atomicAdd(&sh[__float_as_uint(v.y) >> 19], 1u);
            if (v.z > 0.f) atomicAdd(&sh[__float_as_uint(v.z) >> 19], 1u);
            if (v.w > 0.f) atomicAdd(&sh[__float_as_uint(v.w) >> 19], 1u);
        }
        for (int t0 = n4 * 4 + t; t0 < n; t0 += 1024) {
            float v = x[t0];
            if (v > 0.f) atomicAdd(&sh[__float_as_uint(v) >> 19], 1u);
        }
        __syncthreads();
        if (t == 0) {
            long long n_keep = (long long)kptr[0] * num_samples;
            if (n_keep <= 0) { g_bucket = HIST_BINS; g_rem = 0; }
            else {
                long long cum = 0;
                int bkt = -1; unsigned rem = 0;
                for (int i = HIST_BINS - 1; i >= 0; --i) {
                    unsigned c = sh[i];
                    if (cum + (long long)c >= n_keep) {
                        bkt = i; rem = (unsigned)(n_keep - cum); break;
                    }
                    cum += c;
                }
                g_bucket = bkt; g_rem = rem;
            }
            g_c2_count = 0;
        }
        __syncthreads();
        int bucket = g_bucket;
        unsigned r = g_rem;
        if (bucket != HIST_BINS) {
            for (int i = t; i < n; i += 1024) {
                float s = x[i];
                if (s > 0.f) {
                    unsigned u = __float_as_uint(s);
                    int bin = (int)(u >> 19);
                    if (bucket == -1 || bin > bucket) out[i] = s;
                    else if (bin == bucket) {
                        unsigned p = atomicAdd(&g_c2_count, 1u);
                        if (p < CAP2)
                            g_cand2[p] = ((unsigned long long)u << 32) |
                                         (unsigned long long)(unsigned)i;
                    }
                }
            }
            __syncthreads();
            if (bucket >= 0) {
                unsigned m = min(g_c2_count, CAP2);
                for (int i = t; i < RBINS; i += 1024) sh[i] = 0;
                __syncthreads();
                for (unsigned i = t; i < m; i += 1024) {
                    unsigned u = (unsigned)(g_cand2[i] >> 32);
                    atomicAdd(&sh[(u >> 6) & 0x1FFFu], 1u);
                }
                __syncthreads();
                if (t == 0) {
                    unsigned cum = 0, rr = r, b1 = 0;
                    for (int i = RBINS - 1; i >= 0; --i) {
                        unsigned cc = sh[i];
                        if (cum + cc >= rr) { b1 = (unsigned)i; rr -= cum; break; }
                        cum += cc;
                    }
                    misc[0] = b1; misc[1] = rr; misc[2] = 0;
                }
                __syncthreads();
                unsigned b1 = misc[0], r1 = misc[1];
                if (t < 64) sh[t] = 0;
                __syncthreads();
                for (unsigned i = t; i < m; i += 1024) {
                    unsigned long long cv = g_cand2[i];
                    unsigned u = (unsigned)(cv >> 32);
                    if (((u >> 6) & 0x1FFFu) == b1) {
                        unsigned p = atomicAdd(&misc[2], 1u);
                        if (p < EQF_CAP) eqf[p] = cv;
                        atomicAdd(&sh[u & 0x3Fu], 1u);
                    }
                }
                __syncthreads();
                unsigned ec = min(misc[2], (unsigned)EQF_CAP);
                if (t == 0) {
                    unsigned cum = 0, rr = r1, b2 = 0;
                    for (int i = 63; i >= 0; --i) {
                        unsigned cc = sh[i];
                        if (cum + cc >= rr) { b2 = (unsigned)i; rr -= cum; break; }
                        cum += cc;
                    }
                    misc[3] = b2; misc[4] = rr;
                }
                __syncthreads();
                unsigned b2 = misc[3], r2 = misc[4];
                unsigned T = ((unsigned)bucket << 19) | (b1 << 6) | b2;
                for (unsigned i = t; i < ec; i += 1024) {
                    unsigned long long cv = eqf[i];
                    unsigned u   = (unsigned)(cv >> 32);
                    unsigned idx = (unsigned)cv;
                    if (u > T) out[idx] = __uint_as_float(u);
                    else if (u == T) {
                        unsigned rank = 0;
                        for (unsigned j = 0; j < ec; ++j) {
                            unsigned long long cj = eqf[j];
                            if ((unsigned)(cj >> 32) == T && (unsigned)cj < idx) rank++;
                        }
                        if (rank < r2) out[idx] = __uint_as_float(u);
                    }
                }
                __syncthreads();
                for (unsigned i = t; i < m; i += 1024) {
                    unsigned long long cv = g_cand2[i];
                    unsigned u = (unsigned)(cv >> 32);
                    if (((u >> 6) & 0x1FFFu) > b1)
                        out[(unsigned)cv] = __uint_as_float(u);
                }
            }
        }
    }
    __syncthreads();
    if (t == 0) { g_need_full = 0; g_cand_count = 0; g_c2_count = 0; }
}

// ---------------------------------------------------------------------------
extern "C" void kernel_launch(void* const* d_in, const int* in_sizes, int n_in,
                              void* d_out, int out_size) {
    const float* x  = (const float*)d_in[0];
    const int*   kp = (const int*)d_in[1];
    int n = in_sizes[0];
    long long num_samples = (long long)n / 16384;  // last dim = 16384
    int n4 = n / 4;

    sample_kernel<<<SAMPLE_BLOCKS, 256>>>((const float4*)x, n4, n, kp, num_samples);

    int mb = (n4 + 511) / 512;
    if (mb < 1) mb = 1;
    int total_threads = mb * 256;
    main_kernel<<<mb, 256>>>((const float4*)x, (float4*)d_out, n4,
                             x, (float*)d_out, n, total_threads);

    candhist_kernel<<<CH_BLOCKS, 256>>>(kp, num_samples);
    scatter_kernel<<<SC_BLOCKS, 1024>>>((float*)d_out);
    fallback_kernel<<<1, 1024>>>((const float4*)x, n4, x, n, kp, num_samples,
                                 (float*)d_out);
}